// round 1
// baseline (speedup 1.0000x reference)
#include <cuda_runtime.h>

#define IMG_H 200
#define IMG_W 200
#define CHAN 512
#define POOL 7
#define NROI 300

// One block per (roi, pool_y, pool_x). 128 threads, each handling one float4
// (4 channels) of the 512-channel vector: 4 coalesced float4 gathers + 1 store.
__global__ void __launch_bounds__(128) roi_pool_kernel(
    const float* __restrict__ img,   // [200,200,512]
    const int*   __restrict__ rois,  // [300,4] = (x,y,w,h)
    float*       __restrict__ out)   // [300,7,7,512]
{
    const int blk = blockIdx.x;          // 0 .. 300*49-1
    const int roi = blk / (POOL * POOL);
    const int pos = blk % (POOL * POOL);
    const int gy  = pos / POOL;
    const int gx  = pos % POOL;

    const int4 r = ((const int4*)rois)[roi];
    const int x0 = r.x, y0 = r.y, w = r.z, h = r.w;

    // Match reference: ys = y0 + gy * (h/7.0f)
    const float ys = (float)y0 + (float)gy * ((float)h / (float)POOL);
    const float xs = (float)x0 + (float)gx * ((float)w / (float)POOL);
    const int ty = (int)floorf(ys);
    const int tx = (int)floorf(xs);
    const float fy = ys - (float)ty;
    const float fx = xs - (float)tx;
    const int by = min(ty + 1, y0 + h - 1);
    const int bx = min(tx + 1, x0 + w - 1);

    const float4* __restrict__ p00 = (const float4*)(img + ((size_t)ty * IMG_W + tx) * CHAN);
    const float4* __restrict__ p01 = (const float4*)(img + ((size_t)ty * IMG_W + bx) * CHAN);
    const float4* __restrict__ p10 = (const float4*)(img + ((size_t)by * IMG_W + tx) * CHAN);
    const float4* __restrict__ p11 = (const float4*)(img + ((size_t)by * IMG_W + bx) * CHAN);
    float4* __restrict__ o = (float4*)(out + (size_t)blk * CHAN);

    const int c = threadIdx.x;           // 0..127 -> float4 lane

    const float4 v00 = p00[c];
    const float4 v01 = p01[c];
    const float4 v10 = p10[c];
    const float4 v11 = p11[c];

    const float omfx = 1.0f - fx;
    const float omfy = 1.0f - fy;

    // Same association as reference: top = (1-fx)*v00 + fx*v01; then fy blend.
    float4 res;
    {
        float top = omfx * v00.x + fx * v01.x;
        float bot = omfx * v10.x + fx * v11.x;
        res.x = omfy * top + fy * bot;
    }
    {
        float top = omfx * v00.y + fx * v01.y;
        float bot = omfx * v10.y + fx * v11.y;
        res.y = omfy * top + fy * bot;
    }
    {
        float top = omfx * v00.z + fx * v01.z;
        float bot = omfx * v10.z + fx * v11.z;
        res.z = omfy * top + fy * bot;
    }
    {
        float top = omfx * v00.w + fx * v01.w;
        float bot = omfx * v10.w + fx * v11.w;
        res.w = omfy * top + fy * bot;
    }
    o[c] = res;
}

extern "C" void kernel_launch(void* const* d_in, const int* in_sizes, int n_in,
                              void* d_out, int out_size) {
    const float* img  = (const float*)d_in[0];
    const int*   rois = (const int*)d_in[1];
    float*       out  = (float*)d_out;

    const int nblocks = NROI * POOL * POOL;  // 14700
    roi_pool_kernel<<<nblocks, 128>>>(img, rois, out);
}

// round 2
// speedup vs baseline: 1.0025x; 1.0025x over previous
#include <cuda_runtime.h>

#define IMG_H 200
#define IMG_W 200
#define CHAN 512
#define POOL 7
#define NROI 300
#define NPOS (NROI * POOL * POOL)   // 14700

struct Corners {
    const float4* p00;
    const float4* p01;
    const float4* p10;
    const float4* p11;
    float fx, fy;
    bool lx, ly;     // need x-neighbor / y-neighbor loads (weight != 0)
};

__device__ __forceinline__ Corners setup_pos(const int* __restrict__ rois, int pos_id)
{
    const int roi = pos_id / (POOL * POOL);
    const int pos = pos_id % (POOL * POOL);
    const int gy  = pos / POOL;
    const int gx  = pos % POOL;

    const int4 r = __ldg((const int4*)rois + roi);
    const int x0 = r.x, y0 = r.y, w = r.z, h = r.w;

    const float ys = (float)y0 + (float)gy * ((float)h / (float)POOL);
    const float xs = (float)x0 + (float)gx * ((float)w / (float)POOL);
    const int ty = (int)floorf(ys);
    const int tx = (int)floorf(xs);

    Corners c;
    c.fy = ys - (float)ty;
    c.fx = xs - (float)tx;
    c.ly = (c.fy != 0.0f);
    c.lx = (c.fx != 0.0f);

    const int by = min(ty + 1, y0 + h - 1);
    const int bx = min(tx + 1, x0 + w - 1);

    // base offsets in float4 units (CHAN floats = 128 float4)
    c.p00 = (const float4*)nullptr + ((size_t)ty * IMG_W + tx) * (CHAN / 4);
    c.p01 = (const float4*)nullptr + ((size_t)ty * IMG_W + bx) * (CHAN / 4);
    c.p10 = (const float4*)nullptr + ((size_t)by * IMG_W + tx) * (CHAN / 4);
    c.p11 = (const float4*)nullptr + ((size_t)by * IMG_W + bx) * (CHAN / 4);
    return c;
}

__device__ __forceinline__ float4 lerp2d(float4 v00, float4 v01, float4 v10, float4 v11,
                                         float fx, float fy)
{
    const float omfx = 1.0f - fx;
    const float omfy = 1.0f - fy;
    float4 res;
    res.x = omfy * (omfx * v00.x + fx * v01.x) + fy * (omfx * v10.x + fx * v11.x);
    res.y = omfy * (omfx * v00.y + fx * v01.y) + fy * (omfx * v10.y + fx * v11.y);
    res.z = omfy * (omfx * v00.z + fx * v01.z) + fy * (omfx * v10.z + fx * v11.z);
    res.w = omfy * (omfx * v00.w + fx * v01.w) + fy * (omfx * v10.w + fx * v11.w);
    return res;
}

// Each block handles TWO pool positions (one float4 lane per thread per position).
// 8 independent gathers issued up-front per thread -> high MLP.
__global__ void __launch_bounds__(128) roi_pool2_kernel(
    const float* __restrict__ img,   // [200,200,512]
    const int*   __restrict__ rois,  // [300,4]
    float*       __restrict__ out)   // [300,7,7,512]
{
    const int pos0 = blockIdx.x * 2;
    const int pos1 = pos0 + 1;
    const int c = threadIdx.x;       // float4 lane 0..127

    const Corners a = setup_pos(rois, pos0);
    const Corners b = setup_pos(rois, pos1);

    const float4* base = (const float4*)img;
    const float4 zero = make_float4(0.f, 0.f, 0.f, 0.f);

    // Issue all loads before consuming any (conditions are block-uniform).
    float4 a00 = __ldg(base + ((size_t)(a.p00 - (const float4*)nullptr)) + c);
    float4 b00 = __ldg(base + ((size_t)(b.p00 - (const float4*)nullptr)) + c);

    float4 a01 = zero, a10 = zero, a11 = zero;
    float4 b01 = zero, b10 = zero, b11 = zero;

    if (a.lx) a01 = __ldg(base + ((size_t)(a.p01 - (const float4*)nullptr)) + c);
    if (a.ly) a10 = __ldg(base + ((size_t)(a.p10 - (const float4*)nullptr)) + c);
    if (a.lx && a.ly) a11 = __ldg(base + ((size_t)(a.p11 - (const float4*)nullptr)) + c);

    if (b.lx) b01 = __ldg(base + ((size_t)(b.p01 - (const float4*)nullptr)) + c);
    if (b.ly) b10 = __ldg(base + ((size_t)(b.p10 - (const float4*)nullptr)) + c);
    if (b.lx && b.ly) b11 = __ldg(base + ((size_t)(b.p11 - (const float4*)nullptr)) + c);

    float4* o = (float4*)out;
    o[(size_t)pos0 * (CHAN / 4) + c] = lerp2d(a00, a01, a10, a11, a.fx, a.fy);
    o[(size_t)pos1 * (CHAN / 4) + c] = lerp2d(b00, b01, b10, b11, b.fx, b.fy);
}

extern "C" void kernel_launch(void* const* d_in, const int* in_sizes, int n_in,
                              void* d_out, int out_size) {
    const float* img  = (const float*)d_in[0];
    const int*   rois = (const int*)d_in[1];
    float*       out  = (float*)d_out;

    roi_pool2_kernel<<<NPOS / 2, 128>>>(img, rois, out);
}